// round 1
// baseline (speedup 1.0000x reference)
#include <cuda_runtime.h>
#include <cuda_bf16.h>
#include <math.h>

// Problem constants
#define V_  100000
#define D_  128
#define A_  64
#define L_  3
#define N_  20000
#define K_  16

// Device scratch (no allocation allowed in kernel_launch)
__device__ float g_E [(size_t)V_ * A_];   // W_tmp @ W_att[D:2D]   (running, updated per level)
__device__ float g_NT[(size_t)V_ * A_];   // Leaf_emb @ W_att[0:D] (fixed per launch)
__device__ float g_temp[(size_t)N_ * D_]; // per-level temp_emb
__device__ int   g_winner[V_];            // last-wins scatter arbitration

// ---------------------------------------------------------------------------
// winner init: -1 everywhere (must run every launch: graph is replayed)
// ---------------------------------------------------------------------------
__global__ void init_winner_kernel() {
    int i = blockIdx.x * blockDim.x + threadIdx.x;
    if (i < V_) g_winner[i] = -1;
}

// ---------------------------------------------------------------------------
// proj: g_NT[v] = emb[v] @ W_att[0:D], g_E[v] = emb[v] @ W_att[D:2D]
// block = (64 a-threads, 8 rows)
// ---------------------------------------------------------------------------
__global__ void proj_kernel(const float* __restrict__ emb,
                            const float* __restrict__ W_att) {
    __shared__ float s_row[8][D_];
    int v0 = blockIdx.x * 8;
    int tid = threadIdx.y * 64 + threadIdx.x;
    for (int idx = tid; idx < 8 * D_; idx += 512) {
        int r = idx >> 7, d = idx & (D_ - 1);
        int v = v0 + r;
        s_row[r][d] = (v < V_) ? emb[(size_t)v * D_ + d] : 0.f;
    }
    __syncthreads();
    int a = threadIdx.x, r = threadIdx.y;
    int v = v0 + r;
    if (v >= V_) return;
    float st = 0.f, sb = 0.f;
#pragma unroll 8
    for (int d = 0; d < D_; d++) {
        float e = s_row[r][d];
        st = fmaf(e, W_att[d * A_ + a], st);
        sb = fmaf(e, W_att[(D_ + d) * A_ + a], sb);
    }
    g_NT[(size_t)v * A_ + a] = st;
    g_E [(size_t)v * A_ + a] = sb;
}

// ---------------------------------------------------------------------------
// attention: one block (128 threads) per node n.
//   pre_k = sum_a v[a] * lrelu(NT[node,a] + E[neigh_k,a] + b[a])
//   att_k = softmax_k(pre+mask) * softmax_k(weight)
//   temp[n,:] = sum_k att_k * W_tmp[neigh_k,:]
// ---------------------------------------------------------------------------
__global__ void attn_kernel(const float* __restrict__ Wtmp,
                            const int*   __restrict__ nodes,
                            const int*   __restrict__ neighbors,
                            const float* __restrict__ masks,
                            const float* __restrict__ weights,
                            const float* __restrict__ b_att,
                            const float* __restrict__ v_att,
                            int level) {
    int n = blockIdx.x;
    int tid = threadIdx.x;
    int base = level * N_ + n;

    __shared__ int   s_node;
    __shared__ int   s_neigh[K_];
    __shared__ float s_pre[K_];
    __shared__ float s_att[K_];

    if (tid == 0) s_node = nodes[base];
    if (tid < K_) s_neigh[tid] = neighbors[(size_t)base * K_ + tid];
    __syncthreads();
    int node = s_node;

    // ---- phase 1: pre[k]. tid -> (k = tid>>3, g = tid&7), each thread: 8 consecutive a's
    {
        int k = tid >> 3;
        int g = tid & 7;
        int neigh = s_neigh[k];
        const float4* E4  = reinterpret_cast<const float4*>(&g_E [(size_t)neigh * A_]);
        const float4* NT4 = reinterpret_cast<const float4*>(&g_NT[(size_t)node  * A_]);
        const float4* b4  = reinterpret_cast<const float4*>(b_att);
        const float4* v4  = reinterpret_cast<const float4*>(v_att);
        float psum = 0.f;
#pragma unroll
        for (int h = 0; h < 2; h++) {
            float4 e  = E4 [g * 2 + h];
            float4 nt = NT4[g * 2 + h];
            float4 bb = b4 [g * 2 + h];
            float4 vv = v4 [g * 2 + h];
            float z0 = nt.x + e.x + bb.x; z0 = z0 > 0.f ? z0 : 0.01f * z0;
            float z1 = nt.y + e.y + bb.y; z1 = z1 > 0.f ? z1 : 0.01f * z1;
            float z2 = nt.z + e.z + bb.z; z2 = z2 > 0.f ? z2 : 0.01f * z2;
            float z3 = nt.w + e.w + bb.w; z3 = z3 > 0.f ? z3 : 0.01f * z3;
            psum = fmaf(vv.x, z0, psum);
            psum = fmaf(vv.y, z1, psum);
            psum = fmaf(vv.z, z2, psum);
            psum = fmaf(vv.w, z3, psum);
        }
        // reduce over the 8 consecutive lanes of this k-group
#pragma unroll
        for (int off = 4; off; off >>= 1)
            psum += __shfl_down_sync(0xffffffffu, psum, off);
        if (g == 0) s_pre[k] = psum;
    }
    __syncthreads();

    // ---- phase 2: dual softmax on warp 0, lanes 0..15
    if (tid < 32) {
        float pre = (tid < K_) ? s_pre[tid] + masks[(size_t)base * K_ + tid] : -INFINITY;
        float w   = (tid < K_) ? weights[(size_t)base * K_ + tid]            : -INFINITY;
        float m1 = pre, m2 = w;
#pragma unroll
        for (int off = 8; off; off >>= 1) {
            m1 = fmaxf(m1, __shfl_xor_sync(0xffffffffu, m1, off));
            m2 = fmaxf(m2, __shfl_xor_sync(0xffffffffu, m2, off));
        }
        float e1 = (tid < K_) ? __expf(pre - m1) : 0.f;  // max-subtracted; __expf ulp fine here
        float e2 = (tid < K_) ? __expf(w   - m2) : 0.f;
        float s1 = e1, s2 = e2;
#pragma unroll
        for (int off = 8; off; off >>= 1) {
            s1 += __shfl_xor_sync(0xffffffffu, s1, off);
            s2 += __shfl_xor_sync(0xffffffffu, s2, off);
        }
        if (tid < K_) s_att[tid] = (e1 / s1) * (e2 / s2);
    }
    if (tid == 0) atomicMax(&g_winner[node], level * N_ + n);
    __syncthreads();

    // ---- phase 3: temp[n,d] = sum_k att[k] * Wtmp[neigh_k, d]
    float acc = 0.f;
#pragma unroll
    for (int k = 0; k < K_; k++)
        acc = fmaf(s_att[k], Wtmp[(size_t)s_neigh[k] * D_ + tid], acc);
    g_temp[(size_t)n * D_ + tid] = acc;
}

// ---------------------------------------------------------------------------
// scatter: if n is the winner for its node value, write W_tmp row and refresh
// g_E row (E[node] = temp @ W_bot). One block (128 threads) per n.
// ---------------------------------------------------------------------------
__global__ void scatter_kernel(float* __restrict__ Wtmp,
                               const int* __restrict__ nodes,
                               const float* __restrict__ W_att,
                               int level, int updateE) {
    int n = blockIdx.x;
    int node = nodes[level * N_ + n];
    if (g_winner[node] != level * N_ + n) return;
    int tid = threadIdx.x;

    __shared__ float s_t[D_];
    float val = g_temp[(size_t)n * D_ + tid];
    s_t[tid] = val;
    Wtmp[(size_t)node * D_ + tid] = val;
    if (!updateE) return;
    __syncthreads();

    if (tid < A_) {
        float sb = 0.f;
#pragma unroll 8
        for (int d = 0; d < D_; d++)
            sb = fmaf(s_t[d], W_att[(D_ + d) * A_ + tid], sb);
        g_E[(size_t)node * A_ + tid] = sb;
    }
}

// ---------------------------------------------------------------------------
extern "C" void kernel_launch(void* const* d_in, const int* in_sizes, int n_in,
                              void* d_out, int out_size) {
    const float* Leaf_emb  = (const float*)d_in[0];
    const int*   nodes     = (const int*)  d_in[1];
    const int*   neighbors = (const int*)  d_in[2];
    const float* masks     = (const float*)d_in[3];
    const float* weights   = (const float*)d_in[4];
    const float* W_att     = (const float*)d_in[5];
    const float* b_att     = (const float*)d_in[6];
    const float* v_att     = (const float*)d_in[7];
    float* Wtmp = (float*)d_out;

    // W_tmp = Leaf_emb
    cudaMemcpyAsync(Wtmp, Leaf_emb, (size_t)V_ * D_ * sizeof(float),
                    cudaMemcpyDeviceToDevice, 0);

    init_winner_kernel<<<(V_ + 255) / 256, 256>>>();

    dim3 pb(64, 8);
    proj_kernel<<<(V_ + 7) / 8, pb>>>(Leaf_emb, W_att);

    for (int lvl = 0; lvl < L_; lvl++) {
        attn_kernel<<<N_, 128>>>(Wtmp, nodes, neighbors, masks, weights,
                                 b_att, v_att, lvl);
        scatter_kernel<<<N_, 128>>>(Wtmp, nodes, W_att, lvl,
                                    (lvl < L_ - 1) ? 1 : 0);
    }
}

// round 2
// speedup vs baseline: 1.2975x; 1.2975x over previous
#include <cuda_runtime.h>
#include <cuda_bf16.h>
#include <math.h>

// Problem constants
#define V_  100000
#define D_  128
#define A_  64
#define L_  3
#define N_  20000
#define K_  16

typedef unsigned long long ull;

// Device scratch (no allocation allowed anywhere)
__device__ float g_E [(size_t)V_ * A_];   // W_tmp @ W_bot (running)
__device__ float g_NT[(size_t)V_ * A_];   // Leaf_emb @ W_top (fixed)
__device__ float g_temp[(size_t)N_ * D_]; // per-level temp_emb
__device__ int   g_winner[V_];            // last-wins scatter arbitration
__device__ int   g_count[2];              // compacted winner counts (levels 0,1)
__device__ int   g_list[2 * N_];          // compacted winner n-indices

// ---------------- f32x2 packed-FMA helpers (sm_103a FFMA2) -----------------
__device__ __forceinline__ ull pack2(float x, float y) {
    ull r; asm("mov.b64 %0, {%1,%2};" : "=l"(r) : "f"(x), "f"(y)); return r;
}
__device__ __forceinline__ void unpack2(ull v, float& x, float& y) {
    asm("mov.b64 {%0,%1}, %2;" : "=f"(x), "=f"(y) : "l"(v));
}
__device__ __forceinline__ ull fma2(ull a, ull b, ull c) {
    ull d; asm("fma.rn.f32x2 %0, %1, %2, %3;" : "=l"(d) : "l"(a), "l"(b), "l"(c));
    return d;
}

// ---------------------------------------------------------------------------
// init: winner = -1, counts = 0 (must run every replay)
// ---------------------------------------------------------------------------
__global__ void init_winner_kernel() {
    int i = blockIdx.x * blockDim.x + threadIdx.x;
    if (i < V_) g_winner[i] = -1;
    if (i < 2)  g_count[i] = 0;
}

// ---------------------------------------------------------------------------
// proj: NT[v] = emb[v]@W_top, E[v] = emb[v]@W_bot, and Wtmp[v] = emb[v].
// 256 threads, 16 rows/block (grid = 6250, exact). Dynamic smem:
//   sW : float2[128][64]  (top,bottom) pairs  = 64KB
//   s_emb : float[16][128]                    =  8KB
// Each thread: a = tid&63, 4 rows, f32x2 accumulators.
// ---------------------------------------------------------------------------
__global__ void proj_kernel(const float* __restrict__ emb,
                            const float* __restrict__ W_att,
                            float* __restrict__ Wtmp) {
    extern __shared__ float sm[];
    float2* sW   = reinterpret_cast<float2*>(sm);        // [128*64]
    float*  s_emb = sm + 2 * 128 * 64;                   // [16*128]

    const int tid = threadIdx.x;
    const int v0  = blockIdx.x * 16;

    // stage W_att as (top,bottom) pairs
    for (int i = tid; i < 128 * 64; i += 256) {
        int d = i >> 6, a = i & 63;
        sW[i] = make_float2(W_att[d * 64 + a], W_att[(128 + d) * 64 + a]);
    }
    // stage emb rows (float4) and fused Wtmp init
    {
        const float4* src = reinterpret_cast<const float4*>(emb + (size_t)v0 * 128);
        float4* dst = reinterpret_cast<float4*>(Wtmp + (size_t)v0 * 128);
        float4* se  = reinterpret_cast<float4*>(s_emb);
#pragma unroll
        for (int i = tid; i < 16 * 32; i += 256) {
            float4 val = src[i];
            dst[i] = val;
            se[i]  = val;
        }
    }
    __syncthreads();

    const int a  = tid & 63;
    const int rg = tid >> 6;     // 0..3
    ull acc0 = 0, acc1 = 0, acc2 = 0, acc3 = 0;   // (0.f,0.f) bit pattern
    const float* er = s_emb + (rg * 4) * 128;

#pragma unroll 4
    for (int d = 0; d < 128; d++) {
        float2 w = sW[d * 64 + a];
        ull w2 = pack2(w.x, w.y);
        float e0 = er[d];
        float e1 = er[128 + d];
        float e2 = er[256 + d];
        float e3 = er[384 + d];
        acc0 = fma2(pack2(e0, e0), w2, acc0);
        acc1 = fma2(pack2(e1, e1), w2, acc1);
        acc2 = fma2(pack2(e2, e2), w2, acc2);
        acc3 = fma2(pack2(e3, e3), w2, acc3);
    }

    ull accs[4] = {acc0, acc1, acc2, acc3};
#pragma unroll
    for (int r = 0; r < 4; r++) {
        float st, sb; unpack2(accs[r], st, sb);
        size_t v = (size_t)(v0 + rg * 4 + r);
        g_NT[v * 64 + a] = st;
        g_E [v * 64 + a] = sb;
    }
}

// ---------------------------------------------------------------------------
// attention: one block (128 threads) per node n.
// ---------------------------------------------------------------------------
__global__ void attn_kernel(const float* __restrict__ Wtmp,
                            const int*   __restrict__ nodes,
                            const int*   __restrict__ neighbors,
                            const float* __restrict__ masks,
                            const float* __restrict__ weights,
                            const float* __restrict__ b_att,
                            const float* __restrict__ v_att,
                            int level) {
    int n = blockIdx.x;
    int tid = threadIdx.x;
    int base = level * N_ + n;

    __shared__ int   s_node;
    __shared__ int   s_neigh[K_];
    __shared__ float s_pre[K_];
    __shared__ float s_att[K_];

    if (tid == 0) s_node = nodes[base];
    if (tid < K_) s_neigh[tid] = neighbors[(size_t)base * K_ + tid];
    __syncthreads();
    int node = s_node;

    // ---- phase 1: pre[k]; tid -> (k = tid>>3, g = tid&7), 8 a's per thread
    {
        int k = tid >> 3;
        int g = tid & 7;
        int neigh = s_neigh[k];
        const float4* E4  = reinterpret_cast<const float4*>(&g_E [(size_t)neigh * A_]);
        const float4* NT4 = reinterpret_cast<const float4*>(&g_NT[(size_t)node  * A_]);
        const float4* b4  = reinterpret_cast<const float4*>(b_att);
        const float4* v4  = reinterpret_cast<const float4*>(v_att);
        float psum = 0.f;
#pragma unroll
        for (int h = 0; h < 2; h++) {
            float4 e  = E4 [g * 2 + h];
            float4 nt = NT4[g * 2 + h];
            float4 bb = b4 [g * 2 + h];
            float4 vv = v4 [g * 2 + h];
            float z0 = nt.x + e.x + bb.x; z0 = z0 > 0.f ? z0 : 0.01f * z0;
            float z1 = nt.y + e.y + bb.y; z1 = z1 > 0.f ? z1 : 0.01f * z1;
            float z2 = nt.z + e.z + bb.z; z2 = z2 > 0.f ? z2 : 0.01f * z2;
            float z3 = nt.w + e.w + bb.w; z3 = z3 > 0.f ? z3 : 0.01f * z3;
            psum = fmaf(vv.x, z0, psum);
            psum = fmaf(vv.y, z1, psum);
            psum = fmaf(vv.z, z2, psum);
            psum = fmaf(vv.w, z3, psum);
        }
#pragma unroll
        for (int off = 4; off; off >>= 1)
            psum += __shfl_down_sync(0xffffffffu, psum, off);
        if (g == 0) s_pre[k] = psum;
    }
    __syncthreads();

    // ---- phase 2: dual softmax on warp 0
    if (tid < 32) {
        float pre = (tid < K_) ? s_pre[tid] + masks[(size_t)base * K_ + tid] : -INFINITY;
        float w   = (tid < K_) ? weights[(size_t)base * K_ + tid]            : -INFINITY;
        float m1 = pre, m2 = w;
#pragma unroll
        for (int off = 8; off; off >>= 1) {
            m1 = fmaxf(m1, __shfl_xor_sync(0xffffffffu, m1, off));
            m2 = fmaxf(m2, __shfl_xor_sync(0xffffffffu, m2, off));
        }
        float e1 = (tid < K_) ? __expf(pre - m1) : 0.f;
        float e2 = (tid < K_) ? __expf(w   - m2) : 0.f;
        float s1 = e1, s2 = e2;
#pragma unroll
        for (int off = 8; off; off >>= 1) {
            s1 += __shfl_xor_sync(0xffffffffu, s1, off);
            s2 += __shfl_xor_sync(0xffffffffu, s2, off);
        }
        if (tid < K_) s_att[tid] = (e1 / s1) * (e2 / s2);
    }
    if (tid == 0) atomicMax(&g_winner[node], level * N_ + n);
    __syncthreads();

    // ---- phase 3: temp[n,d] = sum_k att[k] * Wtmp[neigh_k, d]
    float acc = 0.f;
#pragma unroll
    for (int k = 0; k < K_; k++)
        acc = fmaf(s_att[k], Wtmp[(size_t)s_neigh[k] * D_ + tid], acc);
    g_temp[(size_t)n * D_ + tid] = acc;
}

// ---------------------------------------------------------------------------
// scatter_write: winners write their W_tmp row (float4) and append n to the
// compact list. 4 n's per 128-thread block (one warp each). grid = 5000.
// ---------------------------------------------------------------------------
__global__ void scatter_write_kernel(float* __restrict__ Wtmp,
                                     const int* __restrict__ nodes,
                                     int level, int appendList) {
    int sub  = threadIdx.x >> 5;
    int lane = threadIdx.x & 31;
    int n = blockIdx.x * 4 + sub;
    if (n >= N_) return;
    int tag = level * N_ + n;
    int node = nodes[tag];
    if (g_winner[node] != tag) return;

    const float4* src = reinterpret_cast<const float4*>(g_temp + (size_t)n * D_);
    float4* dst = reinterpret_cast<float4*>(Wtmp + (size_t)node * D_);
    dst[lane] = src[lane];

    if (appendList && lane == 0) {
        int pos = atomicAdd(&g_count[level], 1);
        g_list[level * N_ + pos] = n;
    }
}

// ---------------------------------------------------------------------------
// eupdate: g_E[node] = temp[n] @ W_bot over the compacted winner list.
// 256 threads, 16 list items/block, grid = 1250 (early-exit past count).
// smem: sWb float[128][64] = 32KB, s_t float[16][128] = 8KB  (static, 40KB)
// ---------------------------------------------------------------------------
__global__ void eupdate_kernel(const int* __restrict__ nodes,
                               const float* __restrict__ W_att,
                               int level) {
    __shared__ float sWb[128 * 64];
    __shared__ float s_t[16 * 128];
    __shared__ int   s_n[16];

    int cnt = g_count[level];
    int base = blockIdx.x * 16;
    if (base >= cnt) return;
    int tid = threadIdx.x;

    for (int i = tid; i < 128 * 64; i += 256) {
        int d = i >> 6, a = i & 63;
        sWb[i] = W_att[(128 + d) * 64 + a];
    }
    if (tid < 16) {
        int item = base + tid;
        s_n[tid] = (item < cnt) ? g_list[level * N_ + item] : -1;
    }
    __syncthreads();
    for (int i = tid; i < 16 * 128; i += 256) {
        int nn = s_n[i >> 7];
        s_t[i] = (nn >= 0) ? g_temp[(size_t)nn * D_ + (i & 127)] : 0.f;
    }
    __syncthreads();

    int a  = tid & 63;
    int rg = tid >> 6;
    float acc[4] = {0.f, 0.f, 0.f, 0.f};
    const float* tr = s_t + (rg * 4) * 128;
#pragma unroll 4
    for (int d = 0; d < 128; d++) {
        float w = sWb[d * 64 + a];
        acc[0] = fmaf(tr[d],       w, acc[0]);
        acc[1] = fmaf(tr[128 + d], w, acc[1]);
        acc[2] = fmaf(tr[256 + d], w, acc[2]);
        acc[3] = fmaf(tr[384 + d], w, acc[3]);
    }
#pragma unroll
    for (int r = 0; r < 4; r++) {
        int nn = s_n[rg * 4 + r];
        if (nn >= 0) {
            int node = nodes[level * N_ + nn];
            g_E[(size_t)node * A_ + a] = acc[r];
        }
    }
}

// ---------------------------------------------------------------------------
extern "C" void kernel_launch(void* const* d_in, const int* in_sizes, int n_in,
                              void* d_out, int out_size) {
    const float* Leaf_emb  = (const float*)d_in[0];
    const int*   nodes     = (const int*)  d_in[1];
    const int*   neighbors = (const int*)  d_in[2];
    const float* masks     = (const float*)d_in[3];
    const float* weights   = (const float*)d_in[4];
    const float* W_att     = (const float*)d_in[5];
    const float* b_att     = (const float*)d_in[6];
    const float* v_att     = (const float*)d_in[7];
    float* Wtmp = (float*)d_out;

    static bool attr_done = false;
    if (!attr_done) {
        cudaFuncSetAttribute(proj_kernel,
                             cudaFuncAttributeMaxDynamicSharedMemorySize,
                             (2 * 128 * 64 + 16 * 128) * (int)sizeof(float));
        attr_done = true;
    }

    init_winner_kernel<<<(V_ + 255) / 256, 256>>>();

    const int proj_smem = (2 * 128 * 64 + 16 * 128) * (int)sizeof(float); // 72KB
    proj_kernel<<<V_ / 16, 256, proj_smem>>>(Leaf_emb, W_att, Wtmp);

    for (int lvl = 0; lvl < L_; lvl++) {
        attn_kernel<<<N_, 128>>>(Wtmp, nodes, neighbors, masks, weights,
                                 b_att, v_att, lvl);
        int appendList = (lvl < L_ - 1) ? 1 : 0;
        scatter_write_kernel<<<(N_ + 3) / 4, 128>>>(Wtmp, nodes, lvl, appendList);
        if (appendList)
            eupdate_kernel<<<(N_ + 15) / 16, 256>>>(nodes, W_att, lvl);
    }
}